// round 8
// baseline (speedup 1.0000x reference)
#include <cuda_runtime.h>
#include <stdint.h>

// Problem constants (fixed by the reference)
#define BB 32
#define TT 256
#define DD 384
#define ML 2048
#define D4 (DD / 4)   // 96 float4 per row
#define RPT 8         // rows per thread
#define NY 8          // y-slices per block
#define RPB (RPT*NY)  // 64 rows per block

// Single fused kernel. Block = (96,8) = 768 threads; each block handles 64
// consecutive output rows of one batch (ML % 64 == 0 -> never straddles).
// Prelude: shfl-based scan of the batch's 256 int32 durations (3 barriers),
// scatter the block's 64-row idx window into smem, then 8-way-ILP gather.
__global__ void lr_fused_kernel(const float4* __restrict__ x,
                                const int* __restrict__ dur,
                                float4* __restrict__ out,
                                float* __restrict__ mel_out) {
    __shared__ int cs[TT];         // inclusive cumsum of durations
    __shared__ int wsum[TT / 32];  // per-warp totals (8)
    __shared__ int sidx[RPB];      // source-token idx for block rows (-1 = pad)

    const int tid  = threadIdx.y * blockDim.x + threadIdx.x;  // 0..767
    const int r0   = blockIdx.x * RPB;       // first output row of this block
    const int b    = r0 >> 11;               // batch = r0 / ML
    const int rloc = r0 & (ML - 1);          // row offset within batch

    // init idx window
    if (tid >= TT && tid < TT + RPB) sidx[tid - TT] = -1;

    int myd = 0;
    if (tid < TT) {
        const int lane = tid & 31;
        const int w    = tid >> 5;           // warp 0..7
        myd = dur[b * TT + tid];

        // warp-level inclusive scan (5 shfl steps)
        int s = myd;
        #pragma unroll
        for (int off = 1; off < 32; off <<= 1) {
            int up = __shfl_up_sync(0xFFFFFFFFu, s, off);
            if (lane >= off) s += up;
        }
        cs[tid] = s;
        if (lane == 31) wsum[w] = s;
    }
    __syncthreads();

    if (tid < TT) {
        const int w = tid >> 5;
        int off = 0;
        #pragma unroll
        for (int i = 0; i < TT / 32 - 1; i++)
            if (i < w) off += wsum[i];
        const int incl = cs[tid] + off;      // inclusive prefix
        cs[tid] = incl;

        // mel_len (float32 tail — proven R4->R5); one block per batch writes
        if (tid == TT - 1 && rloc == 0 && mel_out != nullptr)
            mel_out[b] = (float)incl;
    }
    __syncthreads();

    // Scatter this block's 64-row window: token tid covers [start, end)
    if (tid < TT) {
        const int end   = cs[tid];
        const int start = end - myd;         // exclusive prefix
        int lo = start > rloc ? start : rloc;
        int hi = end < rloc + RPB ? end : rloc + RPB;
        for (int f = lo; f < hi; f++) sidx[f - rloc] = tid;
    }
    __syncthreads();

    // ---- gather: 8 rows per thread, MLP=8 ----
    const int j  = threadIdx.x;              // 0..95
    const int ry = threadIdx.y * RPT;        // this thread's first local row

    int idx[RPT];
    #pragma unroll
    for (int i = 0; i < RPT; i++) idx[i] = sidx[ry + i];

    float4 v[RPT];
    #pragma unroll
    for (int i = 0; i < RPT; i++) {
        v[i] = make_float4(0.f, 0.f, 0.f, 0.f);
        if (idx[i] >= 0) v[i] = __ldg(&x[(b * TT + idx[i]) * D4 + j]);
    }

    const long long base = (long long)(r0 + ry) * D4 + j;
    #pragma unroll
    for (int i = 0; i < RPT; i++) out[base + (long long)i * D4] = v[i];
}

extern "C" void kernel_launch(void* const* d_in, const int* in_sizes, int n_in,
                              void* d_out, int out_size) {
    const float* x   = (const float*)d_in[0];
    const int*   dur = (const int*)d_in[1];   // harness stores duration as int32
    // d_in[2] = max_len (scalar, constant 2048)

    float* out = (float*)d_out;
    const long long main_elems = (long long)BB * ML * DD;
    const long long extra = (long long)out_size - main_elems;
    float* mel_out = (extra > 0) ? (out + main_elems) : nullptr;

    dim3 blk(D4, NY);                    // 768 threads
    dim3 grd((BB * ML) / RPB);           // 1024 blocks
    lr_fused_kernel<<<grd, blk>>>((const float4*)x, dur, (float4*)out, mel_out);
}

// round 9
// speedup vs baseline: 1.2669x; 1.2669x over previous
#include <cuda_runtime.h>
#include <stdint.h>

// Problem constants (fixed by the reference)
#define BB 32
#define TT 256
#define DD 384
#define ML 2048
#define D4 (DD / 4)   // 96 float4 per row
#define RPT 8         // rows per thread
#define NY 4          // y-slices per block (R7 geometry: best occupancy)
#define RPB (RPT*NY)  // 32 rows per block

// Streaming (evict-first) 128-bit store: output is write-once, keep it from
// evicting the hot x / idx working set out of L2.
__device__ __forceinline__ void stg_cs_128(float4* p, float4 v) {
    asm volatile("st.global.cs.v4.f32 [%0], {%1, %2, %3, %4};"
                 :: "l"(p), "f"(v.x), "f"(v.y), "f"(v.z), "f"(v.w)
                 : "memory");
}

// Single fused kernel. Block = (96,4) = 384 threads; each block handles 32
// consecutive output rows of one batch. Prelude: shfl-based scan of the
// batch's 256 int32 durations (3 barriers), scatter the block's 32-row idx
// window into smem, then 8-way-ILP gather with streaming stores.
__global__ void lr_fused_kernel(const float4* __restrict__ x,
                                const int* __restrict__ dur,
                                float4* __restrict__ out,
                                float* __restrict__ mel_out) {
    __shared__ int cs[TT];         // inclusive cumsum of durations
    __shared__ int wsum[TT / 32];  // per-warp totals (8)
    __shared__ int sidx[RPB];      // source-token idx for block rows (-1 = pad)

    const int tid  = threadIdx.y * blockDim.x + threadIdx.x;  // 0..383
    const int r0   = blockIdx.x * RPB;       // first output row of this block
    const int b    = r0 >> 11;               // batch = r0 / ML
    const int rloc = r0 & (ML - 1);          // row offset within batch

    // init idx window
    if (tid >= TT && tid < TT + RPB) sidx[tid - TT] = -1;

    int myd = 0;
    if (tid < TT) {
        const int lane = tid & 31;
        const int w    = tid >> 5;           // warp 0..7
        myd = dur[b * TT + tid];

        // warp-level inclusive scan (5 shfl steps)
        int s = myd;
        #pragma unroll
        for (int off = 1; off < 32; off <<= 1) {
            int up = __shfl_up_sync(0xFFFFFFFFu, s, off);
            if (lane >= off) s += up;
        }
        cs[tid] = s;
        if (lane == 31) wsum[w] = s;
    }
    __syncthreads();

    if (tid < TT) {
        const int w = tid >> 5;
        int off = 0;
        #pragma unroll
        for (int i = 0; i < TT / 32 - 1; i++)
            if (i < w) off += wsum[i];
        const int incl = cs[tid] + off;      // inclusive prefix
        cs[tid] = incl;

        // mel_len (float32 tail — proven R4->R5); one block per batch writes
        if (tid == TT - 1 && rloc == 0 && mel_out != nullptr)
            mel_out[b] = (float)incl;
    }
    __syncthreads();

    // Scatter this block's 32-row window: token tid covers [start, end)
    if (tid < TT) {
        const int end   = cs[tid];
        const int start = end - myd;         // exclusive prefix
        int lo = start > rloc ? start : rloc;
        int hi = end < rloc + RPB ? end : rloc + RPB;
        for (int f = lo; f < hi; f++) sidx[f - rloc] = tid;
    }
    __syncthreads();

    // ---- gather: 8 rows per thread, MLP=8, streaming stores ----
    const int j  = threadIdx.x;              // 0..95
    const int ry = threadIdx.y * RPT;        // this thread's first local row

    int idx[RPT];
    #pragma unroll
    for (int i = 0; i < RPT; i++) idx[i] = sidx[ry + i];

    float4 v[RPT];
    #pragma unroll
    for (int i = 0; i < RPT; i++) {
        v[i] = make_float4(0.f, 0.f, 0.f, 0.f);
        if (idx[i] >= 0) v[i] = __ldg(&x[(b * TT + idx[i]) * D4 + j]);
    }

    float4* basep = (float4*)out + (long long)(r0 + ry) * D4 + j;
    #pragma unroll
    for (int i = 0; i < RPT; i++) stg_cs_128(basep + (long long)i * D4, v[i]);
}

extern "C" void kernel_launch(void* const* d_in, const int* in_sizes, int n_in,
                              void* d_out, int out_size) {
    const float* x   = (const float*)d_in[0];
    const int*   dur = (const int*)d_in[1];   // harness stores duration as int32
    // d_in[2] = max_len (scalar, constant 2048)

    float* out = (float*)d_out;
    const long long main_elems = (long long)BB * ML * DD;
    const long long extra = (long long)out_size - main_elems;
    float* mel_out = (extra > 0) ? (out + main_elems) : nullptr;

    dim3 blk(D4, NY);                    // 384 threads
    dim3 grd((BB * ML) / RPB);           // 2048 blocks
    lr_fused_kernel<<<grd, blk>>>((const float4*)x, dur, (float4*)out, mel_out);
}